// round 6
// baseline (speedup 1.0000x reference)
#include <cuda_runtime.h>
#include <math.h>
#include <stdint.h>

// Problem constants
#define HH 96
#define WWID 96
#define HWSZ (HH * WWID)          // 9216
#define BATCH 8
#define P_TOT (BATCH * HWSZ)      // 73728 pixels
#define C_IN 256
#define C_O 128

// Scratch (device globals — allocation-free per harness rules)
__device__ __align__(16) float g_theta[(size_t)P_TOT * C_O];
__device__ __align__(16) float g_phi  [(size_t)P_TOT * C_O];
__device__ __align__(16) float g_g    [(size_t)P_TOT * C_O];
__device__ __align__(16) float g_wa   [(size_t)P_TOT * C_O];   // stored tf32-rounded
__device__ __align__(16) float g_w3   [3 * C_O * C_IN];        // tf32 w_theta|w_phi|w_g
__device__ __align__(16) float g_wb   [C_IN * C_O];            // tf32 w_back
__device__ float g_tnorm[P_TOT];
__device__ float g_pnorm[P_TOT];

__device__ __forceinline__ uint32_t f2tf32(float x) {
    uint32_t r;
    asm("cvt.rna.tf32.f32 %0, %1;" : "=r"(r) : "f"(x));
    return r;
}

__device__ __forceinline__ void mma_tf32(float c[4],
                                         uint32_t a0, uint32_t a1, uint32_t a2, uint32_t a3,
                                         uint32_t b0, uint32_t b1) {
    asm volatile(
        "mma.sync.aligned.m16n8k8.row.col.f32.tf32.tf32.f32 "
        "{%0,%1,%2,%3},{%4,%5,%6,%7},{%8,%9},{%0,%1,%2,%3};"
        : "+f"(c[0]), "+f"(c[1]), "+f"(c[2]), "+f"(c[3])
        : "r"(a0), "r"(a1), "r"(a2), "r"(a3), "r"(b0), "r"(b1));
}

__device__ __forceinline__ void ldsm_x4(uint32_t& r0, uint32_t& r1, uint32_t& r2, uint32_t& r3,
                                        uint32_t addr) {
    asm volatile("ldmatrix.sync.aligned.m8n8.x4.shared.b16 {%0,%1,%2,%3}, [%4];"
                 : "=r"(r0), "=r"(r1), "=r"(r2), "=r"(r3) : "r"(addr));
}

__device__ __forceinline__ void ldsm_x2(uint32_t& r0, uint32_t& r1, uint32_t addr) {
    asm volatile("ldmatrix.sync.aligned.m8n8.x2.shared.b16 {%0,%1}, [%2];"
                 : "=r"(r0), "=r"(r1) : "r"(addr));
}

#define CP16_CA(dst, src) \
    asm volatile("cp.async.ca.shared.global [%0], [%1], 16;" :: "r"(dst), "l"(src))
#define CP16_CG(dst, src) \
    asm volatile("cp.async.cg.shared.global [%0], [%1], 16;" :: "r"(dst), "l"(src))
#define CP_COMMIT() asm volatile("cp.async.commit_group;")
#define CP_WAIT3()  asm volatile("cp.async.wait_group 3;")

// ---------------------------------------------------------------------------
// Setup: tf32-round all weights once.
// ---------------------------------------------------------------------------
__global__ void cvt_weights(const float* __restrict__ wt, const float* __restrict__ wp,
                            const float* __restrict__ wg, const float* __restrict__ wb)
{
    int i = blockIdx.x * 256 + threadIdx.x;      // 0 .. 32767
    g_w3[i]         = __uint_as_float(f2tf32(wt[i]));
    g_w3[32768 + i] = __uint_as_float(f2tf32(wp[i]));
    g_w3[65536 + i] = __uint_as_float(f2tf32(wg[i]));
    g_wb[i]         = __uint_as_float(f2tf32(wb[i]));
}

// ---------------------------------------------------------------------------
// Pass 1 (tensor, 5-stage cp.async ring, depth 4): theta/phi/g = W@x + bias.
// grid = (3, 576): wsel fastest -> 3 co-resident blocks share the x tile in L2.
// Norms of theta/phi computed in the epilogue.
// dyn smem: 5*2560 (A) + 5*2176 (B) + 128 (part) = 23808 floats = 95232 B.
// ---------------------------------------------------------------------------
__global__ __launch_bounds__(256, 2) void pass1_gemm(
    const float* __restrict__ x,
    const float* __restrict__ b_theta, const float* __restrict__ b_phi,
    const float* __restrict__ b_g)
{
    extern __shared__ __align__(16) float sm[];
    float* As = sm;                    // [5][128][20]
    float* Bs = sm + 5 * 2560;         // [5][16][136]
    float (*stage)[68] = (float(*)[68])sm;
    float* part = sm + 23680;          // [128] per-px sum of squares

    const int tid = threadIdx.x;
    const int lane = tid & 31;
    const int warp = tid >> 5;
    const int warp_m = warp >> 2;
    const int warp_n = warp & 3;
    const int q = lane >> 2;
    const int kl = lane & 3;

    const int wsel = blockIdx.x;
    const int p0 = blockIdx.y * 128;
    const int b = p0 / HWSZ;
    const int hw0 = p0 % HWSZ;

    const float* wsrc = g_w3 + wsel * 32768;
    const float* bias = (wsel == 0) ? b_theta : ((wsel == 1) ? b_phi : b_g);
    float* outp       = (wsel == 0) ? g_theta : ((wsel == 1) ? g_phi : g_g);

    float acc[4][4][4];
#pragma unroll
    for (int mt = 0; mt < 4; ++mt)
#pragma unroll
        for (int nt = 0; nt < 4; ++nt)
#pragma unroll
            for (int i = 0; i < 4; ++i) acc[mt][nt][i] = 0.f;

    const int am   = tid >> 1;
    const int akq0 = (tid & 1) * 2;
    const int bk   = tid >> 4;
    const int bpq0 = (tid & 15) * 2;

    const uint32_t as_base = (uint32_t)__cvta_generic_to_shared(As);
    const uint32_t bs_base = (uint32_t)__cvta_generic_to_shared(Bs);
    const uint32_t a_dst0 = as_base + 4u * (uint32_t)(am * 20 + akq0 * 4);
    const uint32_t b_dst0 = bs_base + 4u * (uint32_t)(bk * 136 + bpq0 * 4);
    const float* a_src0 = wsrc + am * C_IN + akq0 * 4;
    const float* b_src0 = x + (size_t)(b * C_IN + bk) * HWSZ + hw0 + bpq0 * 4;

    const uint32_t a_frag = as_base + 4u * ((uint32_t)(warp_m * 64 + (lane & 15)) * 20u
                                            + (uint32_t)(lane >> 4) * 4u);

#define P1_ISSUE(buf, k0) do { \
    const float* as_ = a_src0 + (k0); \
    uint32_t ad_ = a_dst0 + (uint32_t)(buf) * 10240u; \
    CP16_CA(ad_,      as_); \
    CP16_CA(ad_ + 16, as_ + 4); \
    const float* bs_ = b_src0 + (size_t)(k0) * HWSZ; \
    uint32_t bd_ = b_dst0 + (uint32_t)(buf) * 8704u; \
    CP16_CG(bd_,      bs_); \
    CP16_CG(bd_ + 16, bs_ + 4); \
} while (0)

    P1_ISSUE(0, 0);  CP_COMMIT();
    P1_ISSUE(1, 16); CP_COMMIT();
    P1_ISSUE(2, 32); CP_COMMIT();
    P1_ISSUE(3, 48); CP_COMMIT();

#pragma unroll
    for (int kt = 0; kt < 16; ++kt) {
        const int buf = kt % 5;
        // tile kt ready: committed=4+kt before this wait; <=3 pending => 0..kt drained
        CP_WAIT3();
        __syncthreads();
        // buf (kt+4)%5 == (kt-1)%5 was fully read in iter kt-1 (trailing sync)
        if (kt + 4 < 16) P1_ISSUE((kt + 4) % 5, (kt + 4) * 16);
        CP_COMMIT();    // unconditional: keeps wait-count invariant at the tail

#pragma unroll
        for (int ks = 0; ks < 16; ks += 8) {
            uint32_t af[4][4];
#pragma unroll
            for (int mt = 0; mt < 4; ++mt)
                ldsm_x4(af[mt][0], af[mt][1], af[mt][2], af[mt][3],
                        a_frag + (uint32_t)buf * 10240u + (uint32_t)mt * 1280u + (uint32_t)ks * 4u);
            uint32_t bf[4][2];
            const int kq = ks + kl;
#pragma unroll
            for (int nt = 0; nt < 4; ++nt) {
                int pc = warp_n * 32 + nt * 8 + q;
                bf[nt][0] = __float_as_uint(Bs[buf * 2176 + kq * 136 + pc]);
                bf[nt][1] = __float_as_uint(Bs[buf * 2176 + (kq + 4) * 136 + pc]);
            }
#pragma unroll
            for (int mt = 0; mt < 4; ++mt)
#pragma unroll
                for (int nt = 0; nt < 4; ++nt)
                    mma_tf32(acc[mt][nt], af[mt][0], af[mt][1], af[mt][2], af[mt][3],
                             bf[nt][0], bf[nt][1]);
        }
        __syncthreads();
    }
#undef P1_ISSUE

    float bias_v[4][2];
#pragma unroll
    for (int mt = 0; mt < 4; ++mt)
#pragma unroll
        for (int hi = 0; hi < 2; ++hi)
            bias_v[mt][hi] = bias[warp_m * 64 + mt * 16 + q + hi * 8];

    if (tid < 128) part[tid] = 0.f;

    // Epilogue: stage [px][64ch], coalesced stores + fused norm reduction
#pragma unroll
    for (int h = 0; h < 2; ++h) {
        __syncthreads();
        if (warp_m == h) {
#pragma unroll
            for (int mt = 0; mt < 4; ++mt)
#pragma unroll
                for (int nt = 0; nt < 4; ++nt)
#pragma unroll
                    for (int i = 0; i < 4; ++i) {
                        int px = warp_n * 32 + nt * 8 + 2 * kl + (i & 1);
                        int ch = mt * 16 + q + 8 * (i >> 1);
                        stage[px][ch] = acc[mt][nt][i] + bias_v[mt][i >> 1];
                    }
        }
        __syncthreads();
#pragma unroll
        for (int it = 0; it < 8; ++it) {
            int g = tid + it * 256;
            int px = g >> 4;
            int f  = g & 15;
            float4 v = *(float4*)&stage[px][f * 4];
            ((float4*)outp)[(size_t)(p0 + px) * 32 + h * 16 + f] = v;
            if (wsel < 2) {
                float sq = v.x * v.x + v.y * v.y + v.z * v.z + v.w * v.w;
                sq += __shfl_xor_sync(0xffffffffu, sq, 1);
                sq += __shfl_xor_sync(0xffffffffu, sq, 2);
                sq += __shfl_xor_sync(0xffffffffu, sq, 4);
                sq += __shfl_xor_sync(0xffffffffu, sq, 8);
                if (f == 0) part[px] += sq;   // same thread owns px across h: no race
            }
        }
    }
    __syncthreads();
    if (wsel < 2 && tid < 128) {
        float* np = (wsel == 0) ? g_tnorm : g_pnorm;
        np[p0 + tid] = sqrtf(part[tid]);
    }
}

// ---------------------------------------------------------------------------
// Pass 2: per-pixel 3x3 cosine-sim softmax + weighted avg of g (warp/pixel).
// MLP-restructured: all 9 phi loads in flight, then 9 g loads issued before
// the (independent) shfl reduction chains. Norms precomputed in pass1.
// ---------------------------------------------------------------------------
__global__ __launch_bounds__(256) void pass2_attn()
{
    const int warp = threadIdx.x >> 5;
    const int lane = threadIdx.x & 31;
    const int p = blockIdx.x * 8 + warp;
    const int b  = p / HWSZ;
    const int hw = p % HWSZ;
    const int h = hw / WWID;
    const int w = hw % WWID;

    const float4* th4 = (const float4*)g_theta;
    const float4* ph4 = (const float4*)g_phi;
    const float4* gg4 = (const float4*)g_g;

    int pn[9];
#pragma unroll
    for (int n = 0; n < 9; ++n) {
        int di = n / 3 - 1, dj = n % 3 - 1;
        int hh = min(max(h + di, 0), HH - 1);
        int wn = min(max(w + dj, 0), WWID - 1);
        pn[n] = b * HWSZ + hh * WWID + wn;
    }

    float4 th = th4[(size_t)p * 32 + lane];
    float tn = g_tnorm[p];

    // all 9 neighbor-norm + phi loads in flight together
    float pnv[9];
#pragma unroll
    for (int n = 0; n < 9; ++n) pnv[n] = g_pnorm[pn[n]];
    float4 ph[9];
#pragma unroll
    for (int n = 0; n < 9; ++n) ph[n] = ph4[(size_t)pn[n] * 32 + lane];

    float d[9];
#pragma unroll
    for (int n = 0; n < 9; ++n)
        d[n] = th.x * ph[n].x + th.y * ph[n].y + th.z * ph[n].z + th.w * ph[n].w;

    // issue g loads now; they complete while the shfl butterflies run
    float4 gv[9];
#pragma unroll
    for (int n = 0; n < 9; ++n) gv[n] = gg4[(size_t)pn[n] * 32 + lane];

    // 9 independent butterfly chains, interleaved
#pragma unroll
    for (int off = 16; off; off >>= 1)
#pragma unroll
        for (int n = 0; n < 9; ++n)
            d[n] += __shfl_xor_sync(0xffffffffu, d[n], off);

    // scores + softmax (bounded in [-1,1]: no max-shift needed)
    float s = 0.f;
#pragma unroll
    for (int n = 0; n < 9; ++n) {
        float sc = d[n] / fmaxf(tn * pnv[n], 1e-8f);
        d[n] = __expf(sc);
        s += d[n];
    }
    float inv = 1.f / s;

    float4 acc = make_float4(0.f, 0.f, 0.f, 0.f);
#pragma unroll
    for (int n = 0; n < 9; ++n) {
        float a = d[n] * inv;
        acc.x += a * gv[n].x; acc.y += a * gv[n].y;
        acc.z += a * gv[n].z; acc.w += a * gv[n].w;
    }
    uint4 o;
    o.x = f2tf32(acc.x); o.y = f2tf32(acc.y);
    o.z = f2tf32(acc.z); o.w = f2tf32(acc.w);
    ((uint4*)g_wa)[(size_t)p * 32 + lane] = o;
}

// ---------------------------------------------------------------------------
// Pass 3 (tensor, 5-stage cp.async ring): out = x + W_back@wa + b_back.
// dyn smem: 5*2560*2 = 25600 floats = 102400 B.
// ---------------------------------------------------------------------------
__global__ __launch_bounds__(256, 2) void pass3_gemm(
    const float* __restrict__ x,
    const float* __restrict__ b_back,
    float* __restrict__ out)
{
    extern __shared__ __align__(16) float sm[];
    float* As = sm;                    // [5][128][20]
    float* Bs = sm + 5 * 2560;         // [5][128][20]
    float (*stage)[132] = (float(*)[132])sm;

    const int tid = threadIdx.x;
    const int lane = tid & 31;
    const int warp = tid >> 5;
    const int warp_m = warp >> 2;
    const int warp_n = warp & 3;
    const int q = lane >> 2;
    const int kl = lane & 3;

    const int p0 = blockIdx.x * 128;
    const int b = p0 / HWSZ;
    const int hw0 = p0 % HWSZ;
    const int c0 = blockIdx.y * 128;

    float acc[4][4][4];
#pragma unroll
    for (int mt = 0; mt < 4; ++mt)
#pragma unroll
        for (int nt = 0; nt < 4; ++nt)
#pragma unroll
            for (int i = 0; i < 4; ++i) acc[mt][nt][i] = 0.f;

    const int am   = tid >> 1;
    const int akq0 = (tid & 1) * 2;

    const uint32_t as_base = (uint32_t)__cvta_generic_to_shared(As);
    const uint32_t bs_base = (uint32_t)__cvta_generic_to_shared(Bs);
    const uint32_t a_dst0 = as_base + 4u * (uint32_t)(am * 20 + akq0 * 4);
    const uint32_t b_dst0 = bs_base + 4u * (uint32_t)(am * 20 + akq0 * 4);
    const float* a_src0 = g_wb + (size_t)(c0 + am) * C_O + akq0 * 4;
    const float* b_src0 = g_wa + (size_t)(p0 + am) * C_O + akq0 * 4;

    const uint32_t a_frag = as_base + 4u * ((uint32_t)(warp_m * 64 + (lane & 15)) * 20u
                                            + (uint32_t)(lane >> 4) * 4u);
    const uint32_t b_frag = bs_base + 4u * ((uint32_t)(warp_n * 32 + (lane & 7)) * 20u
                                            + (uint32_t)((lane >> 3) & 1) * 4u);

#define P3_ISSUE(buf, k0) do { \
    const float* as_ = a_src0 + (k0); \
    uint32_t ad_ = a_dst0 + (uint32_t)(buf) * 10240u; \
    CP16_CA(ad_,      as_); \
    CP16_CA(ad_ + 16, as_ + 4); \
    const float* bs_ = b_src0 + (k0); \
    uint32_t bd_ = b_dst0 + (uint32_t)(buf) * 10240u; \
    CP16_CG(bd_,      bs_); \
    CP16_CG(bd_ + 16, bs_ + 4); \
} while (0)

    P3_ISSUE(0, 0);  CP_COMMIT();
    P3_ISSUE(1, 16); CP_COMMIT();
    P3_ISSUE(2, 32); CP_COMMIT();
    P3_ISSUE(3, 48); CP_COMMIT();

#pragma unroll
    for (int kt = 0; kt < 8; ++kt) {
        const int buf = kt % 5;
        CP_WAIT3();
        __syncthreads();
        if (kt + 4 < 8) P3_ISSUE((kt + 4) % 5, (kt + 4) * 16);
        CP_COMMIT();

#pragma unroll
        for (int ks = 0; ks < 16; ks += 8) {
            uint32_t af[4][4];
#pragma unroll
            for (int mt = 0; mt < 4; ++mt)
                ldsm_x4(af[mt][0], af[mt][1], af[mt][2], af[mt][3],
                        a_frag + (uint32_t)buf * 10240u + (uint32_t)mt * 1280u + (uint32_t)ks * 4u);
            uint32_t bf[4][2];
#pragma unroll
            for (int nt = 0; nt < 4; ++nt)
                ldsm_x2(bf[nt][0], bf[nt][1],
                        b_frag + (uint32_t)buf * 10240u + (uint32_t)nt * 640u + (uint32_t)ks * 4u);
#pragma unroll
            for (int mt = 0; mt < 4; ++mt)
#pragma unroll
                for (int nt = 0; nt < 4; ++nt)
                    mma_tf32(acc[mt][nt], af[mt][0], af[mt][1], af[mt][2], af[mt][3],
                             bf[nt][0], bf[nt][1]);
        }
        __syncthreads();
    }
#undef P3_ISSUE

    // Epilogue: stage [ch][px], then coalesced residual-add + store
#pragma unroll
    for (int h = 0; h < 2; ++h) {
        __syncthreads();
        if (warp_m == h) {
#pragma unroll
            for (int mt = 0; mt < 4; ++mt)
#pragma unroll
                for (int nt = 0; nt < 4; ++nt)
#pragma unroll
                    for (int hi = 0; hi < 2; ++hi) {
                        int ch = mt * 16 + q + 8 * hi;
                        int px = warp_n * 32 + nt * 8 + 2 * kl;
                        float2 v2 = make_float2(acc[mt][nt][hi * 2], acc[mt][nt][hi * 2 + 1]);
                        *(float2*)&stage[ch][px] = v2;
                    }
        }
        __syncthreads();
#pragma unroll
        for (int it = 0; it < 8; ++it) {
            int g = tid + it * 256;
            int ch = g >> 5;
            int f  = g & 31;
            int c  = c0 + h * 64 + ch;
            size_t gi = (((size_t)(b * C_IN + c)) * HWSZ + hw0) / 4 + f;
            float4 s = *(float4*)&stage[ch][f * 4];
            float4 xv = ((const float4*)x)[gi];
            float bb = b_back[c];
            float4 o4;
            o4.x = xv.x + bb + s.x;
            o4.y = xv.y + bb + s.y;
            o4.z = xv.z + bb + s.z;
            o4.w = xv.w + bb + s.w;
            ((float4*)out)[gi] = o4;
        }
    }
}

// ---------------------------------------------------------------------------
extern "C" void kernel_launch(void* const* d_in, const int* in_sizes, int n_in,
                              void* d_out, int out_size)
{
    const float* x       = (const float*)d_in[0];
    const float* w_theta = (const float*)d_in[1];
    const float* b_theta = (const float*)d_in[2];
    const float* w_phi   = (const float*)d_in[3];
    const float* b_phi   = (const float*)d_in[4];
    const float* w_g     = (const float*)d_in[5];
    const float* b_g     = (const float*)d_in[6];
    const float* w_back  = (const float*)d_in[7];
    const float* b_back  = (const float*)d_in[8];
    float* out = (float*)d_out;

    const int p1_smem = 23808 * 4;   // 95232 B
    const int p3_smem = 25600 * 4;   // 102400 B
    cudaFuncSetAttribute(pass1_gemm, cudaFuncAttributeMaxDynamicSharedMemorySize, p1_smem);
    cudaFuncSetAttribute(pass3_gemm, cudaFuncAttributeMaxDynamicSharedMemorySize, p3_smem);

    cvt_weights<<<128, 256>>>(w_theta, w_phi, w_g, w_back);

    dim3 g1(3, P_TOT / 128, 1);
    pass1_gemm<<<g1, 256, p1_smem>>>(x, b_theta, b_phi, b_g);

    pass2_attn<<<P_TOT / 8, 256>>>();

    dim3 g3(P_TOT / 128, 2, 1);
    pass3_gemm<<<g3, 256, p3_smem>>>(x, b_back, out);
}

// round 8
// speedup vs baseline: 1.0127x; 1.0127x over previous
#include <cuda_runtime.h>
#include <math.h>
#include <stdint.h>

// Problem constants
#define HH 96
#define WWID 96
#define HWSZ (HH * WWID)          // 9216
#define BATCH 8
#define P_TOT (BATCH * HWSZ)      // 73728 pixels
#define C_IN 256
#define C_O 128

// Scratch (device globals — allocation-free per harness rules)
__device__ __align__(16) float g_theta[(size_t)P_TOT * C_O];
__device__ __align__(16) float g_phi  [(size_t)P_TOT * C_O];
__device__ __align__(16) float g_g    [(size_t)P_TOT * C_O];
__device__ __align__(16) float g_wa   [(size_t)P_TOT * C_O];   // stored tf32-rounded
__device__ __align__(16) float g_w3   [3 * C_O * C_IN];        // tf32 w_theta|w_phi|w_g
__device__ __align__(16) float g_wb   [C_IN * C_O];            // tf32 w_back
__device__ float g_tnorm[P_TOT];
__device__ float g_pnorm[P_TOT];

__device__ __forceinline__ uint32_t f2tf32(float x) {
    uint32_t r;
    asm("cvt.rna.tf32.f32 %0, %1;" : "=r"(r) : "f"(x));
    return r;
}

__device__ __forceinline__ void mma_tf32(float c[4],
                                         uint32_t a0, uint32_t a1, uint32_t a2, uint32_t a3,
                                         uint32_t b0, uint32_t b1) {
    asm volatile(
        "mma.sync.aligned.m16n8k8.row.col.f32.tf32.tf32.f32 "
        "{%0,%1,%2,%3},{%4,%5,%6,%7},{%8,%9},{%0,%1,%2,%3};"
        : "+f"(c[0]), "+f"(c[1]), "+f"(c[2]), "+f"(c[3])
        : "r"(a0), "r"(a1), "r"(a2), "r"(a3), "r"(b0), "r"(b1));
}

__device__ __forceinline__ void ldsm_x4(uint32_t& r0, uint32_t& r1, uint32_t& r2, uint32_t& r3,
                                        uint32_t addr) {
    asm volatile("ldmatrix.sync.aligned.m8n8.x4.shared.b16 {%0,%1,%2,%3}, [%4];"
                 : "=r"(r0), "=r"(r1), "=r"(r2), "=r"(r3) : "r"(addr));
}

__device__ __forceinline__ void ldsm_x2(uint32_t& r0, uint32_t& r1, uint32_t addr) {
    asm volatile("ldmatrix.sync.aligned.m8n8.x2.shared.b16 {%0,%1}, [%2];"
                 : "=r"(r0), "=r"(r1) : "r"(addr));
}

#define CP16_CA(dst, src) \
    asm volatile("cp.async.ca.shared.global [%0], [%1], 16;" :: "r"(dst), "l"(src))
#define CP16_CG(dst, src) \
    asm volatile("cp.async.cg.shared.global [%0], [%1], 16;" :: "r"(dst), "l"(src))
#define CP_COMMIT() asm volatile("cp.async.commit_group;")
#define CP_WAIT2()  asm volatile("cp.async.wait_group 2;")

// ---------------------------------------------------------------------------
// Setup: tf32-round all weights once.
// ---------------------------------------------------------------------------
__global__ void cvt_weights(const float* __restrict__ wt, const float* __restrict__ wp,
                            const float* __restrict__ wg, const float* __restrict__ wb)
{
    int i = blockIdx.x * 256 + threadIdx.x;      // 0 .. 32767
    g_w3[i]         = __uint_as_float(f2tf32(wt[i]));
    g_w3[32768 + i] = __uint_as_float(f2tf32(wp[i]));
    g_w3[65536 + i] = __uint_as_float(f2tf32(wg[i]));
    g_wb[i]         = __uint_as_float(f2tf32(wb[i]));
}

// ---------------------------------------------------------------------------
// Pass 1 (tensor, 4-stage cp.async): theta/phi/g = W(128x256)@x + bias.
// grid = (3, 576): wsel fastest -> 3 co-resident blocks share the x tile in L2.
// Norms of theta/phi computed in the epilogue.
// dyn smem: 4*(2560+2176) + 128 = 19072 floats = 76288 B.
// ---------------------------------------------------------------------------
__global__ __launch_bounds__(256, 2) void pass1_gemm(
    const float* __restrict__ x,
    const float* __restrict__ b_theta, const float* __restrict__ b_phi,
    const float* __restrict__ b_g)
{
    extern __shared__ __align__(16) float sm[];
    float* As = sm;                    // [4][128][20]
    float* Bs = sm + 4 * 2560;         // [4][16][136]
    float (*stage)[68] = (float(*)[68])sm;
    float* part = sm + 18944;          // [128] per-px sum of squares

    const int tid = threadIdx.x;
    const int lane = tid & 31;
    const int warp = tid >> 5;
    const int warp_m = warp >> 2;
    const int warp_n = warp & 3;
    const int q = lane >> 2;
    const int kl = lane & 3;

    const int wsel = blockIdx.x;
    const int p0 = blockIdx.y * 128;
    const int b = p0 / HWSZ;
    const int hw0 = p0 % HWSZ;

    const float* wsrc = g_w3 + wsel * 32768;
    const float* bias = (wsel == 0) ? b_theta : ((wsel == 1) ? b_phi : b_g);
    float* outp       = (wsel == 0) ? g_theta : ((wsel == 1) ? g_phi : g_g);

    float acc[4][4][4];
#pragma unroll
    for (int mt = 0; mt < 4; ++mt)
#pragma unroll
        for (int nt = 0; nt < 4; ++nt)
#pragma unroll
            for (int i = 0; i < 4; ++i) acc[mt][nt][i] = 0.f;

    const int am   = tid >> 1;
    const int akq0 = (tid & 1) * 2;
    const int bk   = tid >> 4;
    const int bpq0 = (tid & 15) * 2;

    const uint32_t as_base = (uint32_t)__cvta_generic_to_shared(As);
    const uint32_t bs_base = (uint32_t)__cvta_generic_to_shared(Bs);
    const uint32_t a_dst0 = as_base + 4u * (uint32_t)(am * 20 + akq0 * 4);
    const uint32_t b_dst0 = bs_base + 4u * (uint32_t)(bk * 136 + bpq0 * 4);
    const float* a_src0 = wsrc + am * C_IN + akq0 * 4;
    const float* b_src0 = x + (size_t)(b * C_IN + bk) * HWSZ + hw0 + bpq0 * 4;

    const uint32_t a_frag = as_base + 4u * ((uint32_t)(warp_m * 64 + (lane & 15)) * 20u
                                            + (uint32_t)(lane >> 4) * 4u);

#define P1_ISSUE(buf, k0) do { \
    const float* as_ = a_src0 + (k0); \
    uint32_t ad_ = a_dst0 + (uint32_t)(buf) * 10240u; \
    CP16_CA(ad_,      as_); \
    CP16_CA(ad_ + 16, as_ + 4); \
    const float* bs_ = b_src0 + (size_t)(k0) * HWSZ; \
    uint32_t bd_ = b_dst0 + (uint32_t)(buf) * 8704u; \
    CP16_CG(bd_,      bs_); \
    CP16_CG(bd_ + 16, bs_ + 4); \
} while (0)

    P1_ISSUE(0, 0);  CP_COMMIT();
    P1_ISSUE(1, 16); CP_COMMIT();
    P1_ISSUE(2, 32); CP_COMMIT();

#pragma unroll 4
    for (int kt = 0; kt < 16; ++kt) {
        const int buf = kt & 3;
        CP_WAIT2();
        __syncthreads();
        if (kt + 3 < 16) P1_ISSUE((kt + 3) & 3, (kt + 3) * 16);
        CP_COMMIT();

#pragma unroll
        for (int ks = 0; ks < 16; ks += 8) {
            uint32_t af[4][4];
#pragma unroll
            for (int mt = 0; mt < 4; ++mt)
                ldsm_x4(af[mt][0], af[mt][1], af[mt][2], af[mt][3],
                        a_frag + (uint32_t)buf * 10240u + (uint32_t)mt * 1280u + (uint32_t)ks * 4u);
            uint32_t bf[4][2];
            const int kq = ks + kl;
#pragma unroll
            for (int nt = 0; nt < 4; ++nt) {
                int pc = warp_n * 32 + nt * 8 + q;
                bf[nt][0] = __float_as_uint(Bs[buf * 2176 + kq * 136 + pc]);
                bf[nt][1] = __float_as_uint(Bs[buf * 2176 + (kq + 4) * 136 + pc]);
            }
#pragma unroll
            for (int mt = 0; mt < 4; ++mt)
#pragma unroll
                for (int nt = 0; nt < 4; ++nt)
                    mma_tf32(acc[mt][nt], af[mt][0], af[mt][1], af[mt][2], af[mt][3],
                             bf[nt][0], bf[nt][1]);
        }
        __syncthreads();
    }
#undef P1_ISSUE

    float bias_v[4][2];
#pragma unroll
    for (int mt = 0; mt < 4; ++mt)
#pragma unroll
        for (int hi = 0; hi < 2; ++hi)
            bias_v[mt][hi] = bias[warp_m * 64 + mt * 16 + q + hi * 8];

    if (tid < 128) part[tid] = 0.f;

    // Epilogue: stage [px][64ch], coalesced stores + fused norm reduction
#pragma unroll
    for (int h = 0; h < 2; ++h) {
        __syncthreads();
        if (warp_m == h) {
#pragma unroll
            for (int mt = 0; mt < 4; ++mt)
#pragma unroll
                for (int nt = 0; nt < 4; ++nt)
#pragma unroll
                    for (int i = 0; i < 4; ++i) {
                        int px = warp_n * 32 + nt * 8 + 2 * kl + (i & 1);
                        int ch = mt * 16 + q + 8 * (i >> 1);
                        stage[px][ch] = acc[mt][nt][i] + bias_v[mt][i >> 1];
                    }
        }
        __syncthreads();
#pragma unroll
        for (int it = 0; it < 8; ++it) {
            int g = tid + it * 256;
            int px = g >> 4;
            int f  = g & 15;
            float4 v = *(float4*)&stage[px][f * 4];
            ((float4*)outp)[(size_t)(p0 + px) * 32 + h * 16 + f] = v;
            if (wsel < 2) {
                float sq = v.x * v.x + v.y * v.y + v.z * v.z + v.w * v.w;
                sq += __shfl_xor_sync(0xffffffffu, sq, 1);
                sq += __shfl_xor_sync(0xffffffffu, sq, 2);
                sq += __shfl_xor_sync(0xffffffffu, sq, 4);
                sq += __shfl_xor_sync(0xffffffffu, sq, 8);
                if (f == 0) part[px] += sq;   // same thread owns px across h: no race
            }
        }
    }
    __syncthreads();
    if (wsel < 2 && tid < 128) {
        float* np = (wsel == 0) ? g_tnorm : g_pnorm;
        np[p0 + tid] = sqrtf(part[tid]);
    }
}

// ---------------------------------------------------------------------------
// Pass 2: per-pixel 3x3 cosine-sim softmax + weighted avg of g (warp/pixel).
// Norms precomputed in pass1: only the dot-product shfl chain remains.
// ---------------------------------------------------------------------------
__global__ __launch_bounds__(256) void pass2_attn()
{
    const int warp = threadIdx.x >> 5;
    const int lane = threadIdx.x & 31;
    const int p = blockIdx.x * 8 + warp;
    const int b  = p / HWSZ;
    const int hw = p % HWSZ;
    const int h = hw / WWID;
    const int w = hw % WWID;

    const float4* th4 = (const float4*)g_theta;
    const float4* ph4 = (const float4*)g_phi;
    const float4* gg4 = (const float4*)g_g;

    float4 th = th4[(size_t)p * 32 + lane];
    float tn = g_tnorm[p];

    int pn[9];
    float sc[9];
#pragma unroll
    for (int n = 0; n < 9; ++n) {
        int di = n / 3 - 1, dj = n % 3 - 1;
        int hh = min(max(h + di, 0), HH - 1);
        int wn = min(max(w + dj, 0), WWID - 1);
        pn[n] = b * HWSZ + hh * WWID + wn;
        float4 ph = ph4[(size_t)pn[n] * 32 + lane];
        float d = th.x * ph.x + th.y * ph.y + th.z * ph.z + th.w * ph.w;
#pragma unroll
        for (int off = 16; off; off >>= 1)
            d += __shfl_xor_sync(0xffffffffu, d, off);
        float den = fmaxf(tn * g_pnorm[pn[n]], 1e-8f);
        sc[n] = d / den;
    }
    // softmax over 9 (scores bounded in [-1,1]: no max-shift needed)
    float s = 0.f;
#pragma unroll
    for (int n = 0; n < 9; ++n) { sc[n] = __expf(sc[n]); s += sc[n]; }
    float inv = 1.f / s;

    float4 acc = make_float4(0.f, 0.f, 0.f, 0.f);
#pragma unroll
    for (int n = 0; n < 9; ++n) {
        float a = sc[n] * inv;
        float4 gv = gg4[(size_t)pn[n] * 32 + lane];
        acc.x += a * gv.x; acc.y += a * gv.y;
        acc.z += a * gv.z; acc.w += a * gv.w;
    }
    uint4 o;
    o.x = f2tf32(acc.x); o.y = f2tf32(acc.y);
    o.z = f2tf32(acc.z); o.w = f2tf32(acc.w);
    ((uint4*)g_wa)[(size_t)p * 32 + lane] = o;
}

// ---------------------------------------------------------------------------
// Pass 3 (tensor, 4-stage cp.async, 3 CTA/SM): out = x + W_back@wa + b_back.
// Tile 128 ch x 64 px. 8 warps as 4x2: warp = 32ch x 32px -> acc[2][4][4].
// A smem [128 c][20], B smem [64 px][20]. grid = (2, P_TOT/64), c fastest.
// dyn smem: ring 4*(2560+1280)=15360 fl; stage [128][68]=8704 fl (union, fits).
// ---------------------------------------------------------------------------
__global__ __launch_bounds__(256, 3) void pass3_gemm(
    const float* __restrict__ x,
    const float* __restrict__ b_back,
    float* __restrict__ out)
{
    extern __shared__ __align__(16) float sm[];
    float* As = sm;                    // [4][128][20]
    float* Bs = sm + 4 * 2560;         // [4][64][20]
    float (*stage)[68] = (float(*)[68])sm;   // [128 ch][64 px + pad] (272B rows: 16B-aligned)

    const int tid = threadIdx.x;
    const int lane = tid & 31;
    const int warp = tid >> 5;
    const int warp_m = warp >> 1;      // 0..3  (32 ch)
    const int warp_n = warp & 1;       // 0..1  (32 px)
    const int q = lane >> 2;
    const int kl = lane & 3;

    const int c0 = blockIdx.x * 128;
    const int p0 = blockIdx.y * 64;
    const int b = p0 / HWSZ;
    const int hw0 = p0 % HWSZ;

    float acc[2][4][4];
#pragma unroll
    for (int mt = 0; mt < 2; ++mt)
#pragma unroll
        for (int nt = 0; nt < 4; ++nt)
#pragma unroll
            for (int i = 0; i < 4; ++i) acc[mt][nt][i] = 0.f;

    // A loader: 512 f4 / 256 thr = 2 each. B loader: 256 f4 / 256 thr = 1 each.
    const int am   = tid >> 1;
    const int akq0 = (tid & 1) * 2;
    const int bm   = tid >> 2;         // 0..63
    const int bkq  = tid & 3;          // 0..3

    const uint32_t as_base = (uint32_t)__cvta_generic_to_shared(As);
    const uint32_t bs_base = (uint32_t)__cvta_generic_to_shared(Bs);
    const uint32_t a_dst0 = as_base + 4u * (uint32_t)(am * 20 + akq0 * 4);
    const uint32_t b_dst0 = bs_base + 4u * (uint32_t)(bm * 20 + bkq * 4);
    const float* a_src0 = g_wb + (size_t)(c0 + am) * C_O + akq0 * 4;
    const float* b_src0 = g_wa + (size_t)(p0 + bm) * C_O + bkq * 4;

    const uint32_t a_frag = as_base + 4u * ((uint32_t)(warp_m * 32 + (lane & 15)) * 20u
                                            + (uint32_t)(lane >> 4) * 4u);
    const uint32_t b_frag = bs_base + 4u * ((uint32_t)(warp_n * 32 + (lane & 7)) * 20u
                                            + (uint32_t)((lane >> 3) & 1) * 4u);

#define P3_ISSUE(buf, k0) do { \
    const float* as_ = a_src0 + (k0); \
    uint32_t ad_ = a_dst0 + (uint32_t)(buf) * 10240u; \
    CP16_CA(ad_,      as_); \
    CP16_CA(ad_ + 16, as_ + 4); \
    const float* bs_ = b_src0 + (k0); \
    uint32_t bd_ = b_dst0 + (uint32_t)(buf) * 5120u; \
    CP16_CG(bd_, bs_); \
} while (0)

    P3_ISSUE(0, 0);  CP_COMMIT();
    P3_ISSUE(1, 16); CP_COMMIT();
    P3_ISSUE(2, 32); CP_COMMIT();

#pragma unroll 4
    for (int kt = 0; kt < 8; ++kt) {
        const int buf = kt & 3;
        CP_WAIT2();
        __syncthreads();
        if (kt + 3 < 8) P3_ISSUE((kt + 3) & 3, (kt + 3) * 16);
        CP_COMMIT();

#pragma unroll
        for (int ks = 0; ks < 16; ks += 8) {
            uint32_t af[2][4];
#pragma unroll
            for (int mt = 0; mt < 2; ++mt)
                ldsm_x4(af[mt][0], af[mt][1], af[mt][2], af[mt][3],
                        a_frag + (uint32_t)buf * 10240u + (uint32_t)mt * 1280u + (uint32_t)ks * 4u);
            uint32_t bf[4][2];
#pragma unroll
            for (int nt = 0; nt < 4; ++nt)
                ldsm_x2(bf[nt][0], bf[nt][1],
                        b_frag + (uint32_t)buf * 5120u + (uint32_t)nt * 640u + (uint32_t)ks * 4u);
#pragma unroll
            for (int mt = 0; mt < 2; ++mt)
#pragma unroll
                for (int nt = 0; nt < 4; ++nt)
                    mma_tf32(acc[mt][nt], af[mt][0], af[mt][1], af[mt][2], af[mt][3],
                             bf[nt][0], bf[nt][1]);
        }
        __syncthreads();
    }
#undef P3_ISSUE

    // Epilogue: stage full tile [128 ch][64 px], then coalesced residual+store
    __syncthreads();
#pragma unroll
    for (int mt = 0; mt < 2; ++mt)
#pragma unroll
        for (int nt = 0; nt < 4; ++nt)
#pragma unroll
            for (int hi = 0; hi < 2; ++hi) {
                int ch = warp_m * 32 + mt * 16 + q + 8 * hi;
                int px = warp_n * 32 + nt * 8 + 2 * kl;
                float2 v2 = make_float2(acc[mt][nt][hi * 2], acc[mt][nt][hi * 2 + 1]);
                *(float2*)&stage[ch][px] = v2;
            }
    __syncthreads();
#pragma unroll
    for (int it = 0; it < 8; ++it) {
        int g = tid + it * 256;
        int ch = g >> 4;              // 0..127
        int f  = g & 15;              // f4 along 64 px
        int c  = c0 + ch;
        size_t gi = (((size_t)(b * C_IN + c)) * HWSZ + hw0) / 4 + f;
        float4 s = *(float4*)&stage[ch][f * 4];
        float4 xv = ((const float4*)x)[gi];
        float bb = b_back[c];
        float4 o4;
        o4.x = xv.x + bb + s.x;
        o4.y = xv.y + bb + s.y;
        o4.z = xv.z + bb + s.z;
        o4.w = xv.w + bb + s.w;
        ((float4*)out)[gi] = o4;
    }
}

// ---------------------------------------------------------------------------
extern "C" void kernel_launch(void* const* d_in, const int* in_sizes, int n_in,
                              void* d_out, int out_size)
{
    const float* x       = (const float*)d_in[0];
    const float* w_theta = (const float*)d_in[1];
    const float* b_theta = (const float*)d_in[2];
    const float* w_phi   = (const float*)d_in[3];
    const float* b_phi   = (const float*)d_in[4];
    const float* w_g     = (const float*)d_in[5];
    const float* b_g     = (const float*)d_in[6];
    const float* w_back  = (const float*)d_in[7];
    const float* b_back  = (const float*)d_in[8];
    float* out = (float*)d_out;

    const int p1_smem = 19072 * 4;   // 76288 B
    const int p3_smem = 15360 * 4;   // 61440 B
    cudaFuncSetAttribute(pass1_gemm, cudaFuncAttributeMaxDynamicSharedMemorySize, p1_smem);
    cudaFuncSetAttribute(pass3_gemm, cudaFuncAttributeMaxDynamicSharedMemorySize, p3_smem);

    cvt_weights<<<128, 256>>>(w_theta, w_phi, w_g, w_back);

    dim3 g1(3, P_TOT / 128, 1);
    pass1_gemm<<<g1, 256, p1_smem>>>(x, b_theta, b_phi, b_g);

    pass2_attn<<<P_TOT / 8, 256>>>();

    dim3 g3(2, P_TOT / 64, 1);
    pass3_gemm<<<g3, 256, p3_smem>>>(x, b_back, out);
}

// round 9
// speedup vs baseline: 1.0340x; 1.0210x over previous
#include <cuda_runtime.h>
#include <math.h>
#include <stdint.h>

// Problem constants
#define HH 96
#define WWID 96
#define HWSZ (HH * WWID)          // 9216
#define BATCH 8
#define P_TOT (BATCH * HWSZ)      // 73728 pixels
#define C_IN 256
#define C_O 128

// Scratch (device globals — allocation-free per harness rules)
__device__ __align__(16) float g_theta[(size_t)P_TOT * C_O];
__device__ __align__(16) float g_phi  [(size_t)P_TOT * C_O];
__device__ __align__(16) float g_g    [(size_t)P_TOT * C_O];
__device__ __align__(16) float g_wa   [(size_t)P_TOT * C_O];   // stored tf32-rounded
__device__ __align__(16) float g_w3   [3 * C_O * C_IN];        // tf32 w_theta|w_phi|w_g
__device__ __align__(16) float g_wb   [C_IN * C_O];            // tf32 w_back
__device__ float g_tnorm[P_TOT];
__device__ float g_pnorm[P_TOT];

__device__ __forceinline__ uint32_t f2tf32(float x) {
    uint32_t r;
    asm("cvt.rna.tf32.f32 %0, %1;" : "=r"(r) : "f"(x));
    return r;
}

__device__ __forceinline__ void mma_tf32(float c[4],
                                         uint32_t a0, uint32_t a1, uint32_t a2, uint32_t a3,
                                         uint32_t b0, uint32_t b1) {
    asm volatile(
        "mma.sync.aligned.m16n8k8.row.col.f32.tf32.tf32.f32 "
        "{%0,%1,%2,%3},{%4,%5,%6,%7},{%8,%9},{%0,%1,%2,%3};"
        : "+f"(c[0]), "+f"(c[1]), "+f"(c[2]), "+f"(c[3])
        : "r"(a0), "r"(a1), "r"(a2), "r"(a3), "r"(b0), "r"(b1));
}

__device__ __forceinline__ void ldsm_x4(uint32_t& r0, uint32_t& r1, uint32_t& r2, uint32_t& r3,
                                        uint32_t addr) {
    asm volatile("ldmatrix.sync.aligned.m8n8.x4.shared.b16 {%0,%1,%2,%3}, [%4];"
                 : "=r"(r0), "=r"(r1), "=r"(r2), "=r"(r3) : "r"(addr));
}

__device__ __forceinline__ void ldsm_x2(uint32_t& r0, uint32_t& r1, uint32_t addr) {
    asm volatile("ldmatrix.sync.aligned.m8n8.x2.shared.b16 {%0,%1}, [%2];"
                 : "=r"(r0), "=r"(r1) : "r"(addr));
}

#define CP16_CA(dst, src) \
    asm volatile("cp.async.ca.shared.global [%0], [%1], 16;" :: "r"(dst), "l"(src))
#define CP16_CG(dst, src) \
    asm volatile("cp.async.cg.shared.global [%0], [%1], 16;" :: "r"(dst), "l"(src))
#define CP_COMMIT() asm volatile("cp.async.commit_group;")
#define CP_WAIT2()  asm volatile("cp.async.wait_group 2;")
#define CP_WAIT0()  asm volatile("cp.async.wait_group 0;")

// ---------------------------------------------------------------------------
// Setup: tf32-round all weights once.
// ---------------------------------------------------------------------------
__global__ void cvt_weights(const float* __restrict__ wt, const float* __restrict__ wp,
                            const float* __restrict__ wg, const float* __restrict__ wb)
{
    int i = blockIdx.x * 256 + threadIdx.x;      // 0 .. 32767
    g_w3[i]         = __uint_as_float(f2tf32(wt[i]));
    g_w3[32768 + i] = __uint_as_float(f2tf32(wp[i]));
    g_w3[65536 + i] = __uint_as_float(f2tf32(wg[i]));
    g_wb[i]         = __uint_as_float(f2tf32(wb[i]));
}

// ---------------------------------------------------------------------------
// Pass 1 (tensor, 4-stage cp.async): theta/phi/g = W(128x256)@x + bias.
// grid = (3, 576): wsel fastest -> 3 co-resident blocks share the x tile in L2.
// Norms of theta/phi computed in the epilogue.
// dyn smem: 4*(2560+2176) + 128 = 19072 floats = 76288 B.
// ---------------------------------------------------------------------------
__global__ __launch_bounds__(256, 2) void pass1_gemm(
    const float* __restrict__ x,
    const float* __restrict__ b_theta, const float* __restrict__ b_phi,
    const float* __restrict__ b_g)
{
    extern __shared__ __align__(16) float sm[];
    float* As = sm;                    // [4][128][20]
    float* Bs = sm + 4 * 2560;         // [4][16][136]
    float (*stage)[68] = (float(*)[68])sm;
    float* part = sm + 18944;          // [128] per-px sum of squares

    const int tid = threadIdx.x;
    const int lane = tid & 31;
    const int warp = tid >> 5;
    const int warp_m = warp >> 2;
    const int warp_n = warp & 3;
    const int q = lane >> 2;
    const int kl = lane & 3;

    const int wsel = blockIdx.x;
    const int p0 = blockIdx.y * 128;
    const int b = p0 / HWSZ;
    const int hw0 = p0 % HWSZ;

    const float* wsrc = g_w3 + wsel * 32768;
    const float* bias = (wsel == 0) ? b_theta : ((wsel == 1) ? b_phi : b_g);
    float* outp       = (wsel == 0) ? g_theta : ((wsel == 1) ? g_phi : g_g);

    float acc[4][4][4];
#pragma unroll
    for (int mt = 0; mt < 4; ++mt)
#pragma unroll
        for (int nt = 0; nt < 4; ++nt)
#pragma unroll
            for (int i = 0; i < 4; ++i) acc[mt][nt][i] = 0.f;

    const int am   = tid >> 1;
    const int akq0 = (tid & 1) * 2;
    const int bk   = tid >> 4;
    const int bpq0 = (tid & 15) * 2;

    const uint32_t as_base = (uint32_t)__cvta_generic_to_shared(As);
    const uint32_t bs_base = (uint32_t)__cvta_generic_to_shared(Bs);
    const uint32_t a_dst0 = as_base + 4u * (uint32_t)(am * 20 + akq0 * 4);
    const uint32_t b_dst0 = bs_base + 4u * (uint32_t)(bk * 136 + bpq0 * 4);
    const float* a_src0 = wsrc + am * C_IN + akq0 * 4;
    const float* b_src0 = x + (size_t)(b * C_IN + bk) * HWSZ + hw0 + bpq0 * 4;

    const uint32_t a_frag = as_base + 4u * ((uint32_t)(warp_m * 64 + (lane & 15)) * 20u
                                            + (uint32_t)(lane >> 4) * 4u);

#define P1_ISSUE(buf, k0) do { \
    const float* as_ = a_src0 + (k0); \
    uint32_t ad_ = a_dst0 + (uint32_t)(buf) * 10240u; \
    CP16_CA(ad_,      as_); \
    CP16_CA(ad_ + 16, as_ + 4); \
    const float* bs_ = b_src0 + (size_t)(k0) * HWSZ; \
    uint32_t bd_ = b_dst0 + (uint32_t)(buf) * 8704u; \
    CP16_CG(bd_,      bs_); \
    CP16_CG(bd_ + 16, bs_ + 4); \
} while (0)

    P1_ISSUE(0, 0);  CP_COMMIT();
    P1_ISSUE(1, 16); CP_COMMIT();
    P1_ISSUE(2, 32); CP_COMMIT();

#pragma unroll 4
    for (int kt = 0; kt < 16; ++kt) {
        const int buf = kt & 3;
        CP_WAIT2();
        __syncthreads();
        if (kt + 3 < 16) P1_ISSUE((kt + 3) & 3, (kt + 3) * 16);
        CP_COMMIT();

#pragma unroll
        for (int ks = 0; ks < 16; ks += 8) {
            uint32_t af[4][4];
#pragma unroll
            for (int mt = 0; mt < 4; ++mt)
                ldsm_x4(af[mt][0], af[mt][1], af[mt][2], af[mt][3],
                        a_frag + (uint32_t)buf * 10240u + (uint32_t)mt * 1280u + (uint32_t)ks * 4u);
            uint32_t bf[4][2];
            const int kq = ks + kl;
#pragma unroll
            for (int nt = 0; nt < 4; ++nt) {
                int pc = warp_n * 32 + nt * 8 + q;
                bf[nt][0] = __float_as_uint(Bs[buf * 2176 + kq * 136 + pc]);
                bf[nt][1] = __float_as_uint(Bs[buf * 2176 + (kq + 4) * 136 + pc]);
            }
#pragma unroll
            for (int mt = 0; mt < 4; ++mt)
#pragma unroll
                for (int nt = 0; nt < 4; ++nt)
                    mma_tf32(acc[mt][nt], af[mt][0], af[mt][1], af[mt][2], af[mt][3],
                             bf[nt][0], bf[nt][1]);
        }
        __syncthreads();
    }
#undef P1_ISSUE

    float bias_v[4][2];
#pragma unroll
    for (int mt = 0; mt < 4; ++mt)
#pragma unroll
        for (int hi = 0; hi < 2; ++hi)
            bias_v[mt][hi] = bias[warp_m * 64 + mt * 16 + q + hi * 8];

    if (tid < 128) part[tid] = 0.f;

    // Epilogue: stage [px][64ch], coalesced stores + fused norm reduction
#pragma unroll
    for (int h = 0; h < 2; ++h) {
        __syncthreads();
        if (warp_m == h) {
#pragma unroll
            for (int mt = 0; mt < 4; ++mt)
#pragma unroll
                for (int nt = 0; nt < 4; ++nt)
#pragma unroll
                    for (int i = 0; i < 4; ++i) {
                        int px = warp_n * 32 + nt * 8 + 2 * kl + (i & 1);
                        int ch = mt * 16 + q + 8 * (i >> 1);
                        stage[px][ch] = acc[mt][nt][i] + bias_v[mt][i >> 1];
                    }
        }
        __syncthreads();
#pragma unroll
        for (int it = 0; it < 8; ++it) {
            int g = tid + it * 256;
            int px = g >> 4;
            int f  = g & 15;
            float4 v = *(float4*)&stage[px][f * 4];
            ((float4*)outp)[(size_t)(p0 + px) * 32 + h * 16 + f] = v;
            if (wsel < 2) {
                float sq = v.x * v.x + v.y * v.y + v.z * v.z + v.w * v.w;
                sq += __shfl_xor_sync(0xffffffffu, sq, 1);
                sq += __shfl_xor_sync(0xffffffffu, sq, 2);
                sq += __shfl_xor_sync(0xffffffffu, sq, 4);
                sq += __shfl_xor_sync(0xffffffffu, sq, 8);
                if (f == 0) part[px] += sq;   // same thread owns px across h: no race
            }
        }
    }
    __syncthreads();
    if (wsel < 2 && tid < 128) {
        float* np = (wsel == 0) ? g_tnorm : g_pnorm;
        np[p0 + tid] = sqrtf(part[tid]);
    }
}

// ---------------------------------------------------------------------------
// Pass 2 (smem-tiled): block = 32-px row strip. phi neighborhood (3x34 px)
// staged in smem once via cp.async, weights computed, then g neighborhood
// staged into the SAME smem and accumulated. ~2.8x less L2 traffic.
// dyn smem: 102*128 (tile) + 32*10 (weights) + 104 (pnorm) = 13480 fl = 53920 B
// grid = P_TOT/32, block 256 (8 warps x 4 px each).
// ---------------------------------------------------------------------------
__global__ __launch_bounds__(256) void pass2_attn()
{
    extern __shared__ __align__(16) float psm[];
    float* tile = psm;                 // [102][128]
    float* wt_s = psm + 102 * 128;     // [32][10]
    float* pn_s = psm + 102 * 128 + 320;   // [102]

    const int tid  = threadIdx.x;
    const int warp = tid >> 5;
    const int lane = tid & 31;

    const int p0 = blockIdx.x * 32;
    const int b  = p0 / HWSZ;
    const int hw = p0 % HWSZ;
    const int h  = hw / WWID;
    const int w0 = hw % WWID;

    const float4* th4 = (const float4*)g_theta;
    const uint32_t tbase = (uint32_t)__cvta_generic_to_shared(tile);

    // ---- phase 1: cp.async phi neighborhood + pnorms ----
#pragma unroll 1
    for (int idx = tid; idx < 3264; idx += 256) {
        int pxl = idx >> 5;            // 0..101
        int f   = idx & 31;
        int r = pxl / 34, c = pxl % 34;
        int hr = min(max(h + r - 1, 0), HH - 1);
        int wc = min(max(w0 + c - 1, 0), WWID - 1);
        const float* src = g_phi + (((size_t)(b * HWSZ + hr * WWID + wc)) << 7) + f * 4;
        CP16_CG(tbase + (uint32_t)idx * 16u, src);
    }
    if (tid < 102) {
        int r = tid / 34, c = tid % 34;
        int hr = min(max(h + r - 1, 0), HH - 1);
        int wc = min(max(w0 + c - 1, 0), WWID - 1);
        pn_s[tid] = g_pnorm[b * HWSZ + hr * WWID + wc];
    }
    CP_COMMIT();
    CP_WAIT0();
    __syncthreads();

    // ---- phase 2: scores + softmax per pixel (4 px per warp) ----
#pragma unroll
    for (int jj = 0; jj < 4; ++jj) {
        int pxl = warp * 4 + jj;       // 0..31
        int p = p0 + pxl;
        float4 th = th4[(size_t)p * 32 + lane];
        float tn = g_tnorm[p];

        float d[9];
#pragma unroll
        for (int n = 0; n < 9; ++n) {
            int di = n / 3, dj = n % 3;
            const float4 ph = *(const float4*)&tile[((di * 34 + pxl + dj) * 32 + lane) * 4];
            d[n] = th.x * ph.x + th.y * ph.y + th.z * ph.z + th.w * ph.w;
        }
#pragma unroll
        for (int off = 16; off; off >>= 1)
#pragma unroll
            for (int n = 0; n < 9; ++n)
                d[n] += __shfl_xor_sync(0xffffffffu, d[n], off);

        float s = 0.f;
#pragma unroll
        for (int n = 0; n < 9; ++n) {
            int di = n / 3, dj = n % 3;
            float den = fmaxf(tn * pn_s[di * 34 + pxl + dj], 1e-8f);
            d[n] = __expf(d[n] / den);     // scores bounded in [-1,1]: no max-shift
            s += d[n];
        }
        float inv = 1.f / s;
        if (lane == 0) {
#pragma unroll
            for (int n = 0; n < 9; ++n) wt_s[pxl * 10 + n] = d[n] * inv;
        }
    }
    __syncthreads();

    // ---- phase 3: cp.async g neighborhood into same tile ----
#pragma unroll 1
    for (int idx = tid; idx < 3264; idx += 256) {
        int pxl = idx >> 5;
        int f   = idx & 31;
        int r = pxl / 34, c = pxl % 34;
        int hr = min(max(h + r - 1, 0), HH - 1);
        int wc = min(max(w0 + c - 1, 0), WWID - 1);
        const float* src = g_g + (((size_t)(b * HWSZ + hr * WWID + wc)) << 7) + f * 4;
        CP16_CG(tbase + (uint32_t)idx * 16u, src);
    }
    CP_COMMIT();
    CP_WAIT0();
    __syncthreads();

    // ---- phase 4: weighted average ----
#pragma unroll
    for (int jj = 0; jj < 4; ++jj) {
        int pxl = warp * 4 + jj;
        int p = p0 + pxl;
        float wt[9];
#pragma unroll
        for (int n = 0; n < 9; ++n) wt[n] = wt_s[pxl * 10 + n];

        float4 acc = make_float4(0.f, 0.f, 0.f, 0.f);
#pragma unroll
        for (int n = 0; n < 9; ++n) {
            int di = n / 3, dj = n % 3;
            const float4 gv = *(const float4*)&tile[((di * 34 + pxl + dj) * 32 + lane) * 4];
            acc.x += wt[n] * gv.x; acc.y += wt[n] * gv.y;
            acc.z += wt[n] * gv.z; acc.w += wt[n] * gv.w;
        }
        uint4 o;
        o.x = f2tf32(acc.x); o.y = f2tf32(acc.y);
        o.z = f2tf32(acc.z); o.w = f2tf32(acc.w);
        ((uint4*)g_wa)[(size_t)p * 32 + lane] = o;
    }
}

// ---------------------------------------------------------------------------
// Pass 3 (tensor, 4-stage cp.async, R5 form): out = x + W_back@wa + b_back.
// Tile 128 ch x 128 px. dyn smem: 4*2560*2 = 20480 floats = 81920 B.
// grid = (576, 2)
// ---------------------------------------------------------------------------
__global__ __launch_bounds__(256, 2) void pass3_gemm(
    const float* __restrict__ x,
    const float* __restrict__ b_back,
    float* __restrict__ out)
{
    extern __shared__ __align__(16) float sm[];
    float* As = sm;                    // [4][128][20]
    float* Bs = sm + 4 * 2560;         // [4][128][20]
    float (*stage)[132] = (float(*)[132])sm;

    const int tid = threadIdx.x;
    const int lane = tid & 31;
    const int warp = tid >> 5;
    const int warp_m = warp >> 2;
    const int warp_n = warp & 3;
    const int q = lane >> 2;
    const int kl = lane & 3;

    const int p0 = blockIdx.x * 128;
    const int b = p0 / HWSZ;
    const int hw0 = p0 % HWSZ;
    const int c0 = blockIdx.y * 128;

    float acc[4][4][4];
#pragma unroll
    for (int mt = 0; mt < 4; ++mt)
#pragma unroll
        for (int nt = 0; nt < 4; ++nt)
#pragma unroll
            for (int i = 0; i < 4; ++i) acc[mt][nt][i] = 0.f;

    const int am   = tid >> 1;
    const int akq0 = (tid & 1) * 2;

    const uint32_t as_base = (uint32_t)__cvta_generic_to_shared(As);
    const uint32_t bs_base = (uint32_t)__cvta_generic_to_shared(Bs);
    const uint32_t a_dst0 = as_base + 4u * (uint32_t)(am * 20 + akq0 * 4);
    const uint32_t b_dst0 = bs_base + 4u * (uint32_t)(am * 20 + akq0 * 4);
    const float* a_src0 = g_wb + (size_t)(c0 + am) * C_O + akq0 * 4;
    const float* b_src0 = g_wa + (size_t)(p0 + am) * C_O + akq0 * 4;

    const uint32_t a_frag = as_base + 4u * ((uint32_t)(warp_m * 64 + (lane & 15)) * 20u
                                            + (uint32_t)(lane >> 4) * 4u);
    const uint32_t b_frag = bs_base + 4u * ((uint32_t)(warp_n * 32 + (lane & 7)) * 20u
                                            + (uint32_t)((lane >> 3) & 1) * 4u);

#define P3_ISSUE(buf, k0) do { \
    const float* as_ = a_src0 + (k0); \
    uint32_t ad_ = a_dst0 + (uint32_t)(buf) * 10240u; \
    CP16_CA(ad_,      as_); \
    CP16_CA(ad_ + 16, as_ + 4); \
    const float* bs_ = b_src0 + (k0); \
    uint32_t bd_ = b_dst0 + (uint32_t)(buf) * 10240u; \
    CP16_CG(bd_,      bs_); \
    CP16_CG(bd_ + 16, bs_ + 4); \
} while (0)

    P3_ISSUE(0, 0);  CP_COMMIT();
    P3_ISSUE(1, 16); CP_COMMIT();
    P3_ISSUE(2, 32); CP_COMMIT();

#pragma unroll 4
    for (int kt = 0; kt < 8; ++kt) {
        const int buf = kt & 3;
        CP_WAIT2();
        __syncthreads();
        if (kt + 3 < 8) P3_ISSUE((kt + 3) & 3, (kt + 3) * 16);
        CP_COMMIT();

#pragma unroll
        for (int ks = 0; ks < 16; ks += 8) {
            uint32_t af[4][4];
#pragma unroll
            for (int mt = 0; mt < 4; ++mt)
                ldsm_x4(af[mt][0], af[mt][1], af[mt][2], af[mt][3],
                        a_frag + (uint32_t)buf * 10240u + (uint32_t)mt * 1280u + (uint32_t)ks * 4u);
            uint32_t bf[4][2];
#pragma unroll
            for (int nt = 0; nt < 4; ++nt)
                ldsm_x2(bf[nt][0], bf[nt][1],
                        b_frag + (uint32_t)buf * 10240u + (uint32_t)nt * 640u + (uint32_t)ks * 4u);
#pragma unroll
            for (int mt = 0; mt < 4; ++mt)
#pragma unroll
                for (int nt = 0; nt < 4; ++nt)
                    mma_tf32(acc[mt][nt], af[mt][0], af[mt][1], af[mt][2], af[mt][3],
                             bf[nt][0], bf[nt][1]);
        }
        __syncthreads();
    }
#undef P3_ISSUE

    // Epilogue: stage [ch][px], then coalesced residual-add + store
#pragma unroll
    for (int h = 0; h < 2; ++h) {
        __syncthreads();
        if (warp_m == h) {
#pragma unroll
            for (int mt = 0; mt < 4; ++mt)
#pragma unroll
                for (int nt = 0; nt < 4; ++nt)
#pragma unroll
                    for (int hi = 0; hi < 2; ++hi) {
                        int ch = mt * 16 + q + 8 * hi;
                        int px = warp_n * 32 + nt * 8 + 2 * kl;
                        float2 v2 = make_float2(acc[mt][nt][hi * 2], acc[mt][nt][hi * 2 + 1]);
                        *(float2*)&stage[ch][px] = v2;
                    }
        }
        __syncthreads();
#pragma unroll
        for (int it = 0; it < 8; ++it) {
            int g = tid + it * 256;
            int ch = g >> 5;
            int f  = g & 31;
            int c  = c0 + h * 64 + ch;
            size_t gi = (((size_t)(b * C_IN + c)) * HWSZ + hw0) / 4 + f;
            float4 s = *(float4*)&stage[ch][f * 4];
            float4 xv = ((const float4*)x)[gi];
            float bb = b_back[c];
            float4 o4;
            o4.x = xv.x + bb + s.x;
            o4.y = xv.y + bb + s.y;
            o4.z = xv.z + bb + s.z;
            o4.w = xv.w + bb + s.w;
            ((float4*)out)[gi] = o4;
        }
    }
}

// ---------------------------------------------------------------------------
extern "C" void kernel_launch(void* const* d_in, const int* in_sizes, int n_in,
                              void* d_out, int out_size)
{
    const float* x       = (const float*)d_in[0];
    const float* w_theta = (const float*)d_in[1];
    const float* b_theta = (const float*)d_in[2];
    const float* w_phi   = (const float*)d_in[3];
    const float* b_phi   = (const float*)d_in[4];
    const float* w_g     = (const float*)d_in[5];
    const float* b_g     = (const float*)d_in[6];
    const float* w_back  = (const float*)d_in[7];
    const float* b_back  = (const float*)d_in[8];
    float* out = (float*)d_out;

    const int p1_smem = 19072 * 4;   // 76288 B
    const int p2_smem = 13480 * 4;   // 53920 B
    const int p3_smem = 20480 * 4;   // 81920 B
    cudaFuncSetAttribute(pass1_gemm, cudaFuncAttributeMaxDynamicSharedMemorySize, p1_smem);
    cudaFuncSetAttribute(pass2_attn, cudaFuncAttributeMaxDynamicSharedMemorySize, p2_smem);
    cudaFuncSetAttribute(pass3_gemm, cudaFuncAttributeMaxDynamicSharedMemorySize, p3_smem);

    cvt_weights<<<128, 256>>>(w_theta, w_phi, w_g, w_back);

    dim3 g1(3, P_TOT / 128, 1);
    pass1_gemm<<<g1, 256, p1_smem>>>(x, b_theta, b_phi, b_g);

    pass2_attn<<<P_TOT / 32, 256, p2_smem>>>();

    dim3 g3(P_TOT / 128, 2, 1);
    pass3_gemm<<<g3, 256, p3_smem>>>(x, b_back, out);
}